// round 5
// baseline (speedup 1.0000x reference)
#include <cuda_runtime.h>
#include <cuda_bf16.h>
#include <cstdint>

#define STARTP 4080

// ---------------------------------------------------------------------------
// Device-global scratch (no allocations allowed)
// ---------------------------------------------------------------------------
__device__ float g_qkv[256 * 6144];                              // fp32 q|k|v (post-RoPE)
__device__ __nv_bfloat16 g_x_h [256*4096], g_x_l [256*4096];     // x planes
__device__ __nv_bfloat16 g_at_h[256*4096], g_at_l[256*4096];     // attn planes

// ---------------------------------------------------------------------------
// helpers
// ---------------------------------------------------------------------------
__device__ __forceinline__ uint32_t packbf(float a, float b) {  // a->lo16, b->hi16
    uint32_t u;
    asm("cvt.rn.bf16x2.f32 %0, %1, %2;" : "=r"(u) : "f"(b), "f"(a));
    return u;
}
// split pair (a,b) into bf16-hi plane word and bf16-lo (residual) plane word
__device__ __forceinline__ void split2(float a, float b, uint32_t& h, uint32_t& l) {
    h = packbf(a, b);
    float ra = a - __uint_as_float(h << 16);
    float rb = b - __uint_as_float(h & 0xffff0000u);
    l = packbf(ra, rb);
}

__device__ __forceinline__ void mma16(float* c, const uint32_t* a,
                                      uint32_t b0, uint32_t b1) {
    asm("mma.sync.aligned.m16n8k16.row.col.f32.bf16.bf16.f32 "
        "{%0,%1,%2,%3}, {%4,%5,%6,%7}, {%8,%9}, {%0,%1,%2,%3};"
        : "+f"(c[0]), "+f"(c[1]), "+f"(c[2]), "+f"(c[3])
        : "r"(a[0]), "r"(a[1]), "r"(a[2]), "r"(a[3]), "r"(b0), "r"(b1));
}

__device__ __forceinline__ void ldsm4(uint32_t* r, uint32_t addr) {
    asm volatile("ldmatrix.sync.aligned.m8n8.x4.shared.b16 {%0,%1,%2,%3}, [%4];"
        : "=r"(r[0]), "=r"(r[1]), "=r"(r[2]), "=r"(r[3]) : "r"(addr));
}
__device__ __forceinline__ void ldsm4t(uint32_t* r, uint32_t addr) {
    asm volatile("ldmatrix.sync.aligned.m8n8.x4.trans.shared.b16 {%0,%1,%2,%3}, [%4];"
        : "=r"(r[0]), "=r"(r[1]), "=r"(r[2]), "=r"(r[3]) : "r"(addr));
}

// ---------------------------------------------------------------------------
// fp32 -> bf16 hi/lo planes (only for x: 4 MB)
// ---------------------------------------------------------------------------
__global__ __launch_bounds__(256) void convert_kernel(
    const float* __restrict__ in, __nv_bfloat16* __restrict__ oh,
    __nv_bfloat16* __restrict__ ol, int n4)
{
    int i = blockIdx.x * 256 + threadIdx.x;
    if (i >= n4) return;
    float4 v = ((const float4*)in)[i];
    uint32_t h0, l0, h1, l1;
    split2(v.x, v.y, h0, l0);
    split2(v.z, v.w, h1, l1);
    ((uint2*)oh)[i] = make_uint2(h0, h1);
    ((uint2*)ol)[i] = make_uint2(l0, l1);
}

// ---------------------------------------------------------------------------
// bf16x3 GEMM, BM=256 (full M: weights read exactly once), BK=32, 256 thr
// (8 warps, 4m x 2n => 2 warps/SMSP). B is fp32 and split hi/lo in-mainloop.
// Optional fused RoPE in the epilogue (QKV projection: cols < 5120).
// ---------------------------------------------------------------------------
template<int BN, bool ROPE>
__global__ __launch_bounds__(256) void gemm_bf16x3(
    const __nv_bfloat16* __restrict__ Ah, const __nv_bfloat16* __restrict__ Al,
    const float* B0, int ldb0, const float* bias0, int split1,
    const float* B1, int ldb1, const float* bias1, int split2_,
    const float* B2, int ldb2, const float* bias2,
    float* __restrict__ C, int ldc,
    const float* __restrict__ cos_t, const float* __restrict__ sin_t)
{
    constexpr int BSTR = BN + 8;      // B smem stride (conflict-free)
    constexpr int NV4  = BN / 4;      // float4 per B row
    constexpr int LB   = BN / 32;     // B float4 loads per thread
    constexpr int NF   = BN / 16;     // n-frags per warp
    constexpr int NG   = BN / 32;     // ldsm n-groups per warp

    extern __shared__ char smraw[];
    __nv_bfloat16* As = (__nv_bfloat16*)smraw;   // [2][2][256][40]
    __nv_bfloat16* Bs = As + 2*2*256*40;         // [2][2][32][BSTR]

    const int n0 = blockIdx.x * BN;

    const float* Bp; int ldb; const float* bias; int nloc;
    if (n0 < split1)       { Bp = B0; ldb = ldb0; bias = bias0; nloc = n0; }
    else if (n0 < split2_) { Bp = B1; ldb = ldb1; bias = bias1; nloc = n0 - split1; }
    else                   { Bp = B2; ldb = ldb2; bias = bias2; nloc = n0 - split2_; }

    const int tid = threadIdx.x, lane = tid & 31, warp = tid >> 5;
    const int g = lane >> 2, tig = lane & 3;
    const int wm = warp & 3, wn = warp >> 2;
    const int lr = lane & 7, mt = lane >> 3;

    const uint32_t sA = (uint32_t)__cvta_generic_to_shared(As);
    const uint32_t sB = (uint32_t)__cvta_generic_to_shared(Bs);

    uint4  pa[8];
    float4 pb[LB];

    auto fetch = [&](int ck) {
        #pragma unroll
        for (int i = 0; i < 8; ++i) {
            int idx = tid + 256 * i;
            int p = idx >> 10, rem = idx & 1023, row = rem >> 2, seg = rem & 3;
            pa[i] = *(const uint4*)((p ? Al : Ah) + (size_t)row * 4096 + ck * 32 + seg * 8);
        }
        #pragma unroll
        for (int i = 0; i < LB; ++i) {
            int idx = tid + 256 * i;
            int row = idx / NV4, c4 = idx % NV4;
            pb[i] = *(const float4*)(Bp + (size_t)(ck * 32 + row) * ldb + nloc + c4 * 4);
        }
    };

    float acc[4][NF][4];
    #pragma unroll
    for (int mf = 0; mf < 4; ++mf)
        #pragma unroll
        for (int nf = 0; nf < NF; ++nf)
            #pragma unroll
            for (int j = 0; j < 4; ++j) acc[mf][nf][j] = 0.f;

    fetch(0);

    for (int ck = 0; ck < 128; ++ck) {
        const int s = ck & 1;

        // store prefetched tile into stage s (A verbatim, B split hi/lo)
        #pragma unroll
        for (int i = 0; i < 8; ++i) {
            int idx = tid + 256 * i;
            int p = idx >> 10, rem = idx & 1023, row = rem >> 2, seg = rem & 3;
            *(uint4*)&As[((s*2 + p)*256 + row)*40 + seg*8] = pa[i];
        }
        #pragma unroll
        for (int i = 0; i < LB; ++i) {
            int idx = tid + 256 * i;
            int row = idx / NV4, c4 = idx % NV4;
            float4 v = pb[i];
            uint32_t h0, l0, h1, l1;
            split2(v.x, v.y, h0, l0);
            split2(v.z, v.w, h1, l1);
            *(uint2*)&Bs[((s*2 + 0)*32 + row)*BSTR + c4*4] = make_uint2(h0, h1);
            *(uint2*)&Bs[((s*2 + 1)*32 + row)*BSTR + c4*4] = make_uint2(l0, l1);
        }

        if (ck + 1 < 128) fetch(ck + 1);
        __syncthreads();

        #pragma unroll
        for (int ks = 0; ks < 2; ++ks) {
            uint32_t ah[4][4], al[4][4];
            #pragma unroll
            for (int mf = 0; mf < 4; ++mf) {
                int row = wm*64 + mf*16 + (mt & 1)*8 + lr;
                int col = ks*16 + (mt >> 1)*8;
                ldsm4(ah[mf], sA + (uint32_t)((((s*2+0)*256 + row)*40 + col)*2));
                ldsm4(al[mf], sA + (uint32_t)((((s*2+1)*256 + row)*40 + col)*2));
            }
            #pragma unroll
            for (int ng = 0; ng < NG; ++ng) {
                int brow = ks*16 + (mt & 1)*8 + lr;
                int bcol = wn*(BN/2) + ng*16 + (mt >> 1)*8;
                uint32_t bh[4], bl[4];
                ldsm4t(bh, sB + (uint32_t)((((s*2+0)*32 + brow)*BSTR + bcol)*2));
                ldsm4t(bl, sB + (uint32_t)((((s*2+1)*32 + brow)*BSTR + bcol)*2));
                #pragma unroll
                for (int h = 0; h < 2; ++h) {
                    int nf = ng*2 + h;
                    #pragma unroll
                    for (int mf = 0; mf < 4; ++mf) {
                        mma16(acc[mf][nf], ah[mf], bh[2*h], bh[2*h+1]);
                        mma16(acc[mf][nf], ah[mf], bl[2*h], bl[2*h+1]);
                        mma16(acc[mf][nf], al[mf], bh[2*h], bh[2*h+1]);
                    }
                }
            }
        }
        __syncthreads();
    }

    // epilogue: bias + optional fused RoPE (pairs (c0,c1)/(c2,c3) are the
    // even/odd column pairs RoPE rotates)
    #pragma unroll
    for (int mf = 0; mf < 4; ++mf) {
        int r0 = wm*64 + mf*16 + g;           // rows r0 and r0+8
        #pragma unroll
        for (int nf = 0; nf < NF; ++nf) {
            int cl = wn*(BN/2) + nf*8 + 2*tig;
            int gc = n0 + cl;
            float b0v = bias[nloc + cl], b1v = bias[nloc + cl + 1];
            float c0 = acc[mf][nf][0] + b0v, c1 = acc[mf][nf][1] + b1v;
            float c2 = acc[mf][nf][2] + b0v, c3 = acc[mf][nf][3] + b1v;
            if (ROPE && gc < 5120) {
                int p = (gc & 127) >> 1;
                float cs0 = cos_t[(r0 & 15)*64 + p],       sn0 = sin_t[(r0 & 15)*64 + p];
                float cs1 = cos_t[((r0 + 8) & 15)*64 + p], sn1 = sin_t[((r0 + 8) & 15)*64 + p];
                float t0 = c0*cs0 - c1*sn0, t1 = c0*sn0 + c1*cs0;
                float t2 = c2*cs1 - c3*sn1, t3 = c2*sn1 + c3*cs1;
                c0 = t0; c1 = t1; c2 = t2; c3 = t3;
            }
            *(float2*)(C + (size_t)r0 * ldc + gc)       = make_float2(c0, c1);
            *(float2*)(C + (size_t)(r0 + 8) * ldc + gc) = make_float2(c2, c3);
        }
    }
}

// ---------------------------------------------------------------------------
// bf16x3 flash attention, 384 threads:
//   warps 0-7 : consumers. head = w>>1, half = w&1; each handles 32 of the 64
//               keys per tile with its own online-softmax state. Q fragments
//               live in persistent smem planes (ldmatrix per tile).
//   warps 8-11: producers (fp32 K/V -> hi/lo split -> smem planes).
// Halves merged exactly at the end; output written as bf16 hi/lo planes.
// ---------------------------------------------------------------------------
__global__ __launch_bounds__(384, 1) void attn_bf16x3(
    const float* __restrict__ cache_k, const float* __restrict__ cache_v)
{
    extern __shared__ char smraw[];
    // [0, 17408)      Qh plane  [64][136]
    // [17408, 34816)  Ql plane
    // [34816, 174080) K/V planes: 8 x [64][136] (Kh[2],Kl[2],Vh[2],Vl[2])
    __nv_bfloat16* Qh = (__nv_bfloat16*)smraw;
    __nv_bfloat16* Ql = Qh + 8704;
    __nv_bfloat16* KV = Ql + 8704;
    float* mbuf  = (float*)(smraw + 34816);            // merge: [4][16][128]
    float* lmbuf = (float*)(smraw + 34816 + 32768);    // merge: [4][16][2]

    const int tid = threadIdx.x, lane = tid & 31, w = tid >> 5;
    const int g = lane >> 2, tig = lane & 3;
    const int lr = lane & 7, mt = lane >> 3;
    const int b = blockIdx.x >> 3, kvh = blockIdx.x & 7;
    const int head = w >> 1, half = w & 1;      // consumers only
    const int ptid = tid - 256;                 // producers only
    const float scale = 0.08838834764831843f;   // 1/sqrt(128)
    const float* qkv = g_qkv;

    // ---- stage Q: fp32 (scaled) -> bf16 hi/lo planes ----
    for (int i = tid; i < 64 * 32; i += 384) {
        int r = i >> 5, c4 = (i & 31) << 2;
        const float* src = qkv + (size_t)(b * 16 + (r & 15)) * 6144
                         + (kvh * 4 + (r >> 4)) * 128 + c4;
        float4 v = *(const float4*)src;
        v.x *= scale; v.y *= scale; v.z *= scale; v.w *= scale;
        uint32_t h0, l0, h1, l1;
        split2(v.x, v.y, h0, l0);
        split2(v.z, v.w, h1, l1);
        *(uint32_t*)&Qh[r*136 + c4]     = h0;
        *(uint32_t*)&Qh[r*136 + c4 + 2] = h1;
        *(uint32_t*)&Ql[r*136 + c4]     = l0;
        *(uint32_t*)&Ql[r*136 + c4 + 2] = l1;
    }
    __syncthreads();

    const uint32_t qh_b = (uint32_t)__cvta_generic_to_shared(Qh);
    const uint32_t ql_b = (uint32_t)__cvta_generic_to_shared(Ql);
    const uint32_t kv_b = (uint32_t)__cvta_generic_to_shared(KV);

    float oacc[16][4];
    #pragma unroll
    for (int i = 0; i < 16; ++i)
        #pragma unroll
        for (int j = 0; j < 4; ++j) oacc[i][j] = 0.f;
    float mA = -1e30f, mB = -1e30f, lA = 0.f, lB = 0.f;

    // producer: fp32 K/V tile -> split -> bf16 planes (stage t&1)
    auto produce = [&](int t) {
        int e0 = (t & 1) * 8704;
        #pragma unroll 4
        for (int i = 0; i < 16; ++i) {
            int id = ptid + 128 * i;
            int row = id >> 5, c4 = (id & 31) << 2;
            int key = t * 64 + row;
            const float *ks, *vs;
            if (key < STARTP) {
                size_t base = ((size_t)(b * 4096 + key) * 8 + kvh) * 128 + c4;
                ks = cache_k + base; vs = cache_v + base;
            } else {
                size_t rb = (size_t)(b * 16 + key - STARTP) * 6144 + kvh * 128 + c4;
                ks = qkv + rb + 4096; vs = qkv + rb + 5120;
            }
            float4 kvv = *(const float4*)ks;
            float4 vvv = *(const float4*)vs;
            uint32_t h0, l0, h1, l1;
            int e = e0 + row * 136 + c4;
            split2(kvv.x, kvv.y, h0, l0); split2(kvv.z, kvv.w, h1, l1);
            *(uint32_t*)&KV[e]            = h0; *(uint32_t*)&KV[e + 2]            = h1;
            *(uint32_t*)&KV[2*8704 + e]   = l0; *(uint32_t*)&KV[2*8704 + e + 2]   = l1;
            split2(vvv.x, vvv.y, h0, l0); split2(vvv.z, vvv.w, h1, l1);
            *(uint32_t*)&KV[4*8704 + e]   = h0; *(uint32_t*)&KV[4*8704 + e + 2]   = h1;
            *(uint32_t*)&KV[6*8704 + e]   = l0; *(uint32_t*)&KV[6*8704 + e + 2]   = l1;
        }
    };

    if (w >= 8) produce(0);
    __syncthreads();

    for (int t = 0; t < 64; ++t) {
        const int s = t & 1;

        if (w >= 8) {
            if (t + 1 < 64) produce(t + 1);
        } else {
            const uint32_t kh_o = (uint32_t)((s      * 8704) * 2);
            const uint32_t kl_o = (uint32_t)(((2+s)  * 8704) * 2);
            const uint32_t vh_o = (uint32_t)(((4+s)  * 8704) * 2);
            const uint32_t vl_o = (uint32_t)(((6+s)  * 8704) * 2);

            // ---- S = Q K^T over this warp's 32 keys ----
            float sacc[4][4];
            #pragma unroll
            for (int nf = 0; nf < 4; ++nf)
                #pragma unroll
                for (int j = 0; j < 4; ++j) sacc[nf][j] = 0.f;

            #pragma unroll
            for (int kk = 0; kk < 8; ++kk) {
                int qrow = head*16 + (mt & 1)*8 + lr;
                int qcol = kk*16 + (mt >> 1)*8;
                uint32_t qfh[4], qfl[4];
                ldsm4(qfh, qh_b + (uint32_t)((qrow*136 + qcol)*2));
                ldsm4(qfl, ql_b + (uint32_t)((qrow*136 + qcol)*2));
                #pragma unroll
                for (int nfp = 0; nfp < 2; ++nfp) {
                    int krow = half*32 + (nfp*2 + (mt >> 1))*8 + lr;
                    int kcol = kk*16 + (mt & 1)*8;
                    uint32_t off = (uint32_t)((krow*136 + kcol)*2);
                    uint32_t bh[4], bl[4];
                    ldsm4(bh, kv_b + kh_o + off);
                    ldsm4(bl, kv_b + kl_o + off);
                    #pragma unroll
                    for (int h = 0; h < 2; ++h) {
                        int nf = nfp*2 + h;
                        mma16(sacc[nf], qfh, bh[2*h], bh[2*h+1]);
                        mma16(sacc[nf], qfh, bl[2*h], bl[2*h+1]);
                        mma16(sacc[nf], qfl, bh[2*h], bh[2*h+1]);
                    }
                }
            }

            if (t == 63 && half == 1) {   // causal mask (keys 4064..4095)
                #pragma unroll
                for (int nf = 0; nf < 4; ++nf) {
                    int key = 4064 + nf*8 + 2*tig;
                    if (key     > STARTP + g)     sacc[nf][0] = -1e30f;
                    if (key + 1 > STARTP + g)     sacc[nf][1] = -1e30f;
                    if (key     > STARTP + g + 8) sacc[nf][2] = -1e30f;
                    if (key + 1 > STARTP + g + 8) sacc[nf][3] = -1e30f;
                }
            }

            // ---- online softmax (rows g and g+8) ----
            float tmA = -1e30f, tmB = -1e30f;
            #pragma unroll
            for (int nf = 0; nf < 4; ++nf) {
                tmA = fmaxf(tmA, fmaxf(sacc[nf][0], sacc[nf][1]));
                tmB = fmaxf(tmB, fmaxf(sacc[nf][2], sacc[nf][3]));
            }
            tmA = fmaxf(tmA, __shfl_xor_sync(0xffffffffu, tmA, 1));
            tmA = fmaxf(tmA, __shfl_xor_sync(0xffffffffu, tmA, 2));
            tmB = fmaxf(tmB, __shfl_xor_sync(0xffffffffu, tmB, 1));
            tmB = fmaxf(tmB, __shfl_xor_sync(0xffffffffu, tmB, 2));

            float mnA = fmaxf(mA, tmA), mnB = fmaxf(mB, tmB);
            float cA = __expf(mA - mnA), cB = __expf(mB - mnB);
            float psA = 0.f, psB = 0.f;
            #pragma unroll
            for (int nf = 0; nf < 4; ++nf) {
                sacc[nf][0] = __expf(sacc[nf][0] - mnA);
                sacc[nf][1] = __expf(sacc[nf][1] - mnA);
                sacc[nf][2] = __expf(sacc[nf][2] - mnB);
                sacc[nf][3] = __expf(sacc[nf][3] - mnB);
                psA += sacc[nf][0] + sacc[nf][1];
                psB += sacc[nf][2] + sacc[nf][3];
            }
            psA += __shfl_xor_sync(0xffffffffu, psA, 1);
            psA += __shfl_xor_sync(0xffffffffu, psA, 2);
            psB += __shfl_xor_sync(0xffffffffu, psB, 1);
            psB += __shfl_xor_sync(0xffffffffu, psB, 2);
            lA = lA * cA + psA; lB = lB * cB + psB;
            mA = mnA; mB = mnB;
            #pragma unroll
            for (int i = 0; i < 16; ++i) {
                oacc[i][0] *= cA; oacc[i][1] *= cA;
                oacc[i][2] *= cB; oacc[i][3] *= cB;
            }

            // ---- O += P V over this warp's 32 keys ----
            #pragma unroll
            for (int kf = 0; kf < 2; ++kf) {
                uint32_t pah[4], pal[4];
                split2(sacc[2*kf][0],   sacc[2*kf][1],   pah[0], pal[0]);
                split2(sacc[2*kf][2],   sacc[2*kf][3],   pah[1], pal[1]);
                split2(sacc[2*kf+1][0], sacc[2*kf+1][1], pah[2], pal[2]);
                split2(sacc[2*kf+1][2], sacc[2*kf+1][3], pah[3], pal[3]);
                #pragma unroll
                for (int np = 0; np < 8; ++np) {
                    int vrow = half*32 + kf*16 + (mt & 1)*8 + lr;
                    int vcol = (np*2 + (mt >> 1))*8;
                    uint32_t off = (uint32_t)((vrow*136 + vcol)*2);
                    uint32_t vh[4], vl[4];
                    ldsm4t(vh, kv_b + vh_o + off);
                    ldsm4t(vl, kv_b + vl_o + off);
                    #pragma unroll
                    for (int h = 0; h < 2; ++h) {
                        int nf2 = np*2 + h;
                        mma16(oacc[nf2], pah, vh[2*h], vh[2*h+1]);
                        mma16(oacc[nf2], pah, vl[2*h], vl[2*h+1]);
                        mma16(oacc[nf2], pal, vh[2*h], vh[2*h+1]);
                    }
                }
            }
        }
        __syncthreads();   // stage s consumed; stage s^1 stores visible
    }

    // ---- merge the two key-halves of each head (exact) ----
    if (w < 8 && half == 1) {
        #pragma unroll
        for (int nf2 = 0; nf2 < 16; ++nf2) {
            int col = nf2*8 + 2*tig;
            float* rA = mbuf + ((head*16 + g    )*128 + col);
            float* rB = mbuf + ((head*16 + g + 8)*128 + col);
            rA[0] = oacc[nf2][0]; rA[1] = oacc[nf2][1];
            rB[0] = oacc[nf2][2]; rB[1] = oacc[nf2][3];
        }
        if (tig == 0) {
            lmbuf[(head*16 + g    )*2 + 0] = mA;
            lmbuf[(head*16 + g    )*2 + 1] = lA;
            lmbuf[(head*16 + g + 8)*2 + 0] = mB;
            lmbuf[(head*16 + g + 8)*2 + 1] = lB;
        }
    }
    __syncthreads();
    if (w < 8 && half == 0) {
        float m1A = lmbuf[(head*16 + g    )*2 + 0];
        float l1A = lmbuf[(head*16 + g    )*2 + 1];
        float m1B = lmbuf[(head*16 + g + 8)*2 + 0];
        float l1B = lmbuf[(head*16 + g + 8)*2 + 1];
        float msA = fmaxf(mA, m1A), msB = fmaxf(mB, m1B);
        float c0A = __expf(mA - msA), c1A = __expf(m1A - msA);
        float c0B = __expf(mB - msB), c1B = __expf(m1B - msB);
        float rAi = 1.f / (lA*c0A + l1A*c1A);
        float rBi = 1.f / (lB*c0B + l1B*c1B);

        size_t baseA = (size_t)(b*16 + g    ) * 4096 + (kvh*4 + head) * 128;
        size_t baseB = (size_t)(b*16 + g + 8) * 4096 + (kvh*4 + head) * 128;
        #pragma unroll
        for (int nf2 = 0; nf2 < 16; ++nf2) {
            int col = nf2*8 + 2*tig;
            const float* pA = mbuf + ((head*16 + g    )*128 + col);
            const float* pB = mbuf + ((head*16 + g + 8)*128 + col);
            float oA0 = (oacc[nf2][0]*c0A + pA[0]*c1A) * rAi;
            float oA1 = (oacc[nf2][1]*c0A + pA[1]*c1A) * rAi;
            float oB0 = (oacc[nf2][2]*c0B + pB[0]*c1B) * rBi;
            float oB1 = (oacc[nf2][3]*c0B + pB[1]*c1B) * rBi;
            uint32_t h, l;
            split2(oA0, oA1, h, l);
            *(uint32_t*)&g_at_h[baseA + col] = h;
            *(uint32_t*)&g_at_l[baseA + col] = l;
            split2(oB0, oB1, h, l);
            *(uint32_t*)&g_at_h[baseB + col] = h;
            *(uint32_t*)&g_at_l[baseB + col] = l;
        }
    }
}

// ---------------------------------------------------------------------------
extern "C" void kernel_launch(void* const* d_in, const int* in_sizes, int n_in,
                              void* d_out, int out_size)
{
    const float* x  = (const float*)d_in[0];
    const float* fc = (const float*)d_in[1];
    const float* fs = (const float*)d_in[2];
    const float* ck = (const float*)d_in[4];
    const float* cv = (const float*)d_in[5];
    const float* wq = (const float*)d_in[6];
    const float* bq = (const float*)d_in[7];
    const float* wk = (const float*)d_in[8];
    const float* bk = (const float*)d_in[9];
    const float* wv = (const float*)d_in[10];
    const float* bv = (const float*)d_in[11];
    const float* wo = (const float*)d_in[12];
    const float* bo = (const float*)d_in[13];
    float* out = (float*)d_out;

    __nv_bfloat16 *x_h, *x_l, *at_h, *at_l;
    float* qkv;
    cudaGetSymbolAddress((void**)&x_h,  g_x_h);  cudaGetSymbolAddress((void**)&x_l,  g_x_l);
    cudaGetSymbolAddress((void**)&at_h, g_at_h); cudaGetSymbolAddress((void**)&at_l, g_at_l);
    cudaGetSymbolAddress((void**)&qkv,  g_qkv);

    const int gemm_smem64 = (2*2*256*40 + 2*2*32*72) * 2;   // 100352 B
    const int gemm_smem32 = (2*2*256*40 + 2*2*32*40) * 2;   //  92160 B
    const int attn_smem   = 34816 + 8 * 8704 * 2;           // 174080 B
    cudaFuncSetAttribute(gemm_bf16x3<64, true>,
                         cudaFuncAttributeMaxDynamicSharedMemorySize, gemm_smem64);
    cudaFuncSetAttribute(gemm_bf16x3<32, false>,
                         cudaFuncAttributeMaxDynamicSharedMemorySize, gemm_smem32);
    cudaFuncSetAttribute(attn_bf16x3,
                         cudaFuncAttributeMaxDynamicSharedMemorySize, attn_smem);

    // 1) split x -> bf16 planes
    convert_kernel<<<1024, 256>>>(x, x_h, x_l, 256*4096/4);

    // 2) fused QKV projection + RoPE (fp32 out into g_qkv)
    gemm_bf16x3<64, true><<<96, 256, gemm_smem64>>>(
        x_h, x_l,
        wq, 4096, bq, 4096,
        wk, 1024, bk, 5120,
        wv, 1024, bv,
        qkv, 6144, fc, fs);

    // 3) attention (8 consumer + 4 producer warps; writes bf16 planes)
    attn_bf16x3<<<128, 384, attn_smem>>>(ck, cv);

    // 4) output projection -> d_out (fp32), BN=32 => 128 blocks
    gemm_bf16x3<32, false><<<128, 256, gemm_smem32>>>(
        at_h, at_l,
        wo, 4096, bo, 1 << 30,
        wo, 4096, bo, 1 << 30,
        wo, 4096, bo,
        out, 4096, nullptr, nullptr);
}

// round 6
// speedup vs baseline: 2.1157x; 2.1157x over previous
#include <cuda_runtime.h>
#include <cuda_bf16.h>
#include <cstdint>

#define STARTP 4080

// ---------------------------------------------------------------------------
// Device-global scratch (no allocations allowed)
// ---------------------------------------------------------------------------
__device__ float g_qkv[256 * 6144];                              // fp32 q|k|v (post-RoPE)
__device__ __nv_bfloat16 g_x_h [256*4096], g_x_l [256*4096];     // x planes
__device__ __nv_bfloat16 g_at_h[256*4096], g_at_l[256*4096];     // attn planes

// ---------------------------------------------------------------------------
// helpers
// ---------------------------------------------------------------------------
__device__ __forceinline__ uint32_t packbf(float a, float b) {  // a->lo16, b->hi16
    uint32_t u;
    asm("cvt.rn.bf16x2.f32 %0, %1, %2;" : "=r"(u) : "f"(b), "f"(a));
    return u;
}
// split pair (a,b) into bf16-hi plane word and bf16-lo (residual) plane word
__device__ __forceinline__ void split2(float a, float b, uint32_t& h, uint32_t& l) {
    h = packbf(a, b);
    float ra = a - __uint_as_float(h << 16);
    float rb = b - __uint_as_float(h & 0xffff0000u);
    l = packbf(ra, rb);
}

__device__ __forceinline__ void mma16(float* c, const uint32_t* a,
                                      uint32_t b0, uint32_t b1) {
    asm("mma.sync.aligned.m16n8k16.row.col.f32.bf16.bf16.f32 "
        "{%0,%1,%2,%3}, {%4,%5,%6,%7}, {%8,%9}, {%0,%1,%2,%3};"
        : "+f"(c[0]), "+f"(c[1]), "+f"(c[2]), "+f"(c[3])
        : "r"(a[0]), "r"(a[1]), "r"(a[2]), "r"(a[3]), "r"(b0), "r"(b1));
}

__device__ __forceinline__ void ldsm4(uint32_t* r, uint32_t addr) {
    asm volatile("ldmatrix.sync.aligned.m8n8.x4.shared.b16 {%0,%1,%2,%3}, [%4];"
        : "=r"(r[0]), "=r"(r[1]), "=r"(r[2]), "=r"(r[3]) : "r"(addr));
}
__device__ __forceinline__ void ldsm4t(uint32_t* r, uint32_t addr) {
    asm volatile("ldmatrix.sync.aligned.m8n8.x4.trans.shared.b16 {%0,%1,%2,%3}, [%4];"
        : "=r"(r[0]), "=r"(r[1]), "=r"(r[2]), "=r"(r[3]) : "r"(addr));
}

// ---------------------------------------------------------------------------
// fp32 -> bf16 hi/lo planes (only for x: 4 MB, ~2 us)
// ---------------------------------------------------------------------------
__global__ __launch_bounds__(256) void convert_kernel(
    const float* __restrict__ in, __nv_bfloat16* __restrict__ oh,
    __nv_bfloat16* __restrict__ ol, int n4)
{
    int i = blockIdx.x * 256 + threadIdx.x;
    if (i >= n4) return;
    float4 v = ((const float4*)in)[i];
    uint32_t h0, l0, h1, l1;
    split2(v.x, v.y, h0, l0);
    split2(v.z, v.w, h1, l1);
    ((uint2*)oh)[i] = make_uint2(h0, h1);
    ((uint2*)ol)[i] = make_uint2(l0, l1);
}

// ---------------------------------------------------------------------------
// bf16x3 GEMM: C[M,N] = A[M,4096] @ B[4096,N] + bias (fp32 out).
// A: pre-split bf16 planes. B: fp32, register-prefetched + split in-loop.
// Block 64M x BN, BK=32, 128 thr (warps 2m x 2n), 2-stage smem.
// BN=64 -> 39 KB smem, ~2.6 CTA/SM residency at these grids.
// Optional fused RoPE epilogue (QKV projection: global cols < 5120).
// ---------------------------------------------------------------------------
template<int BN, bool ROPE>
__global__ __launch_bounds__(128) void gemm_bf16x3(
    const __nv_bfloat16* __restrict__ Ah, const __nv_bfloat16* __restrict__ Al,
    const float* B0, int ldb0, const float* bias0, int split1,
    const float* B1, int ldb1, const float* bias1, int split2_,
    const float* B2, int ldb2, const float* bias2,
    float* __restrict__ C, int ldc,
    const float* __restrict__ cos_t, const float* __restrict__ sin_t)
{
    constexpr int BSTR = BN + 8;      // B smem stride
    constexpr int NV4  = BN / 4;      // float4 per B row
    constexpr int LB   = 32 * NV4 / 128;   // B float4 loads per thread
    constexpr int NF   = BN / 16;     // n-frags (8 cols) per warp
    constexpr int NG   = BN / 32;     // ldsm n-groups per warp

    extern __shared__ char smraw[];
    __nv_bfloat16* As = (__nv_bfloat16*)smraw;      // [2][2][64][40]
    __nv_bfloat16* Bs = As + 2*2*64*40;             // [2][2][32][BSTR]

    const int n0 = blockIdx.x * BN;
    const int m0 = blockIdx.y * 64;

    const float* Bp; int ldb; const float* bias; int nloc;
    if (n0 < split1)       { Bp = B0; ldb = ldb0; bias = bias0; nloc = n0; }
    else if (n0 < split2_) { Bp = B1; ldb = ldb1; bias = bias1; nloc = n0 - split1; }
    else                   { Bp = B2; ldb = ldb2; bias = bias2; nloc = n0 - split2_; }

    const int tid = threadIdx.x, lane = tid & 31, warp = tid >> 5;
    const int g = lane >> 2, tig = lane & 3;
    const int wm = warp & 1, wn = warp >> 1;
    const int lr = lane & 7, mt = lane >> 3;

    const uint32_t sA = (uint32_t)__cvta_generic_to_shared(As);
    const uint32_t sB = (uint32_t)__cvta_generic_to_shared(Bs);

    uint4  pa[4];
    float4 pb[LB];

    auto fetch = [&](int ck) {
        #pragma unroll
        for (int i = 0; i < 4; ++i) {
            int idx = tid + 128 * i;
            int p = idx >> 8, rem = idx & 255, row = rem >> 2, seg = rem & 3;
            pa[i] = *(const uint4*)((p ? Al : Ah)
                + (size_t)(m0 + row) * 4096 + ck * 32 + seg * 8);
        }
        #pragma unroll
        for (int i = 0; i < LB; ++i) {
            int idx = tid + 128 * i;
            int row = idx / NV4, c4 = idx % NV4;
            pb[i] = *(const float4*)(Bp + (size_t)(ck * 32 + row) * ldb + nloc + c4 * 4);
        }
    };

    float acc[2][NF][4];
    #pragma unroll
    for (int mf = 0; mf < 2; ++mf)
        #pragma unroll
        for (int nf = 0; nf < NF; ++nf)
            #pragma unroll
            for (int j = 0; j < 4; ++j) acc[mf][nf][j] = 0.f;

    fetch(0);

    for (int ck = 0; ck < 128; ++ck) {
        const int s = ck & 1;

        // store prefetched tile into stage s (A verbatim, B split hi/lo)
        #pragma unroll
        for (int i = 0; i < 4; ++i) {
            int idx = tid + 128 * i;
            int p = idx >> 8, rem = idx & 255, row = rem >> 2, seg = rem & 3;
            *(uint4*)&As[((s*2 + p)*64 + row)*40 + seg*8] = pa[i];
        }
        #pragma unroll
        for (int i = 0; i < LB; ++i) {
            int idx = tid + 128 * i;
            int row = idx / NV4, c4 = idx % NV4;
            float4 v = pb[i];
            uint32_t h0, l0, h1, l1;
            split2(v.x, v.y, h0, l0);
            split2(v.z, v.w, h1, l1);
            *(uint2*)&Bs[((s*2 + 0)*32 + row)*BSTR + c4*4] = make_uint2(h0, h1);
            *(uint2*)&Bs[((s*2 + 1)*32 + row)*BSTR + c4*4] = make_uint2(l0, l1);
        }

        if (ck + 1 < 128) fetch(ck + 1);   // issue LDGs early; consumed next iter
        __syncthreads();

        #pragma unroll
        for (int ks = 0; ks < 2; ++ks) {
            int k0 = ks * 16;
            uint32_t ah[2][4], al[2][4];
            #pragma unroll
            for (int mf = 0; mf < 2; ++mf) {
                int row = wm*32 + mf*16 + (mt & 1)*8 + lr;
                int col = k0 + (mt >> 1)*8;
                ldsm4(ah[mf], sA + (uint32_t)((((s*2+0)*64 + row)*40 + col)*2));
                ldsm4(al[mf], sA + (uint32_t)((((s*2+1)*64 + row)*40 + col)*2));
            }
            #pragma unroll
            for (int ng = 0; ng < NG; ++ng) {
                int brow = k0 + (mt & 1)*8 + lr;
                int bcol = wn*(BN/2) + ng*16 + (mt >> 1)*8;
                uint32_t bh[4], bl[4];
                ldsm4t(bh, sB + (uint32_t)((((s*2+0)*32 + brow)*BSTR + bcol)*2));
                ldsm4t(bl, sB + (uint32_t)((((s*2+1)*32 + brow)*BSTR + bcol)*2));
                #pragma unroll
                for (int h = 0; h < 2; ++h) {
                    int nf = ng*2 + h;
                    #pragma unroll
                    for (int mf = 0; mf < 2; ++mf) {
                        mma16(acc[mf][nf], ah[mf], bh[2*h], bh[2*h+1]);
                        mma16(acc[mf][nf], ah[mf], bl[2*h], bl[2*h+1]);
                        mma16(acc[mf][nf], al[mf], bh[2*h], bh[2*h+1]);
                    }
                }
            }
        }
    }

    __syncthreads();
    // epilogue: bias + optional fused RoPE (acc pairs (c0,c1)/(c2,c3) are the
    // even/odd column pairs RoPE rotates)
    #pragma unroll
    for (int mf = 0; mf < 2; ++mf) {
        int r0 = m0 + wm*32 + mf*16 + g;      // rows r0 and r0+8 (global)
        #pragma unroll
        for (int nf = 0; nf < NF; ++nf) {
            int cl = wn*(BN/2) + nf*8 + 2*tig;
            int gc = n0 + cl;
            float b0v = bias[nloc + cl], b1v = bias[nloc + cl + 1];
            float c0 = acc[mf][nf][0] + b0v, c1 = acc[mf][nf][1] + b1v;
            float c2 = acc[mf][nf][2] + b0v, c3 = acc[mf][nf][3] + b1v;
            if (ROPE && gc < 5120) {
                int p = (gc & 127) >> 1;
                float cs0 = cos_t[(r0 & 15)*64 + p],       sn0 = sin_t[(r0 & 15)*64 + p];
                float cs1 = cos_t[((r0 + 8) & 15)*64 + p], sn1 = sin_t[((r0 + 8) & 15)*64 + p];
                float t0 = c0*cs0 - c1*sn0, t1 = c0*sn0 + c1*cs0;
                float t2 = c2*cs1 - c3*sn1, t3 = c2*sn1 + c3*cs1;
                c0 = t0; c1 = t1; c2 = t2; c3 = t3;
            }
            *(float2*)(C + (size_t)r0 * ldc + gc)       = make_float2(c0, c1);
            *(float2*)(C + (size_t)(r0 + 8) * ldc + gc) = make_float2(c2, c3);
        }
    }
}

// ---------------------------------------------------------------------------
// bf16x3 flash attention, warp-specialized (R4-proven structure).
// Block = (b, kvh), 256 threads. Warps 0-3: consumers (head w, MMA+softmax).
// Warps 4-7: producers (fp32 K/V loads -> hi/lo split -> smem planes).
// ---------------------------------------------------------------------------
__global__ __launch_bounds__(256, 1) void attn_bf16x3(
    const float* __restrict__ cache_k, const float* __restrict__ cache_v)
{
    extern __shared__ char smraw[];
    __nv_bfloat16* Kh = (__nv_bfloat16*)smraw;   // [2][64][136]
    __nv_bfloat16* Kl = Kh + 2*8704;
    __nv_bfloat16* Vh = Kl + 2*8704;
    __nv_bfloat16* Vl = Vh + 2*8704;
    float* Qs = (float*)smraw;                   // staging only (pre-loop)

    const int tid = threadIdx.x, lane = tid & 31, w = tid >> 5;
    const int g = lane >> 2, tig = lane & 3;
    const int lr = lane & 7, mt = lane >> 3;
    const int b = blockIdx.x >> 3, kvh = blockIdx.x & 7;
    const int ptid = tid & 127;                  // producer linear id
    const float scale = 0.08838834764831843f;    // 1/sqrt(128)
    const float* qkv = g_qkv;

    // ---- stage Q (scaled fp32) ----
    for (int i = tid; i < 64 * 32; i += 256) {
        int r = i >> 5, c4 = (i & 31) << 2;
        const float* src = qkv + (size_t)(b * 16 + (r & 15)) * 6144
                         + (kvh * 4 + (r >> 4)) * 128 + c4;
        float4 v = *(const float4*)src;
        Qs[r * 132 + c4 + 0] = v.x * scale;
        Qs[r * 132 + c4 + 1] = v.y * scale;
        Qs[r * 132 + c4 + 2] = v.z * scale;
        Qs[r * 132 + c4 + 3] = v.w * scale;
    }
    __syncthreads();

    // consumers lift Q to bf16 hi/lo fragments
    uint32_t qh[8][4], ql[8][4];
    if (w < 4) {
        #pragma unroll
        for (int kk = 0; kk < 8; ++kk) {
            const float* r0 = Qs + (w*16 + g    ) * 132 + kk*16;
            const float* r1 = Qs + (w*16 + g + 8) * 132 + kk*16;
            split2(r0[2*tig],     r0[2*tig + 1], qh[kk][0], ql[kk][0]);
            split2(r1[2*tig],     r1[2*tig + 1], qh[kk][1], ql[kk][1]);
            split2(r0[2*tig + 8], r0[2*tig + 9], qh[kk][2], ql[kk][2]);
            split2(r1[2*tig + 8], r1[2*tig + 9], qh[kk][3], ql[kk][3]);
        }
    }
    __syncthreads();   // Qs region free; producers may overwrite (K planes)

    const uint32_t kh_b = (uint32_t)__cvta_generic_to_shared(Kh);
    const uint32_t kl_b = (uint32_t)__cvta_generic_to_shared(Kl);
    const uint32_t vh_b = (uint32_t)__cvta_generic_to_shared(Vh);
    const uint32_t vl_b = (uint32_t)__cvta_generic_to_shared(Vl);

    float oacc[16][4];
    #pragma unroll
    for (int i = 0; i < 16; ++i)
        #pragma unroll
        for (int j = 0; j < 4; ++j) oacc[i][j] = 0.f;
    float mA = -1e30f, mB = -1e30f, lA = 0.f, lB = 0.f;

    // producer warps: load fp32 K/V tile, split, store bf16 planes
    auto produce = [&](int t) {
        int s = t & 1;
        #pragma unroll 4
        for (int i = 0; i < 16; ++i) {
            int id = ptid + 128 * i;
            int row = id >> 5, c4 = (id & 31) << 2;
            int key = t * 64 + row;
            const float *ks, *vs;
            if (key < STARTP) {
                size_t base = ((size_t)(b * 4096 + key) * 8 + kvh) * 128 + c4;
                ks = cache_k + base; vs = cache_v + base;
            } else {
                size_t rb = (size_t)(b * 16 + key - STARTP) * 6144 + kvh * 128 + c4;
                ks = qkv + rb + 4096; vs = qkv + rb + 5120;
            }
            float4 kv = *(const float4*)ks;
            float4 vv = *(const float4*)vs;
            uint32_t h0, l0, h1, l1;
            int e = s * 8704 + row * 136 + c4;
            split2(kv.x, kv.y, h0, l0); split2(kv.z, kv.w, h1, l1);
            *(uint32_t*)&Kh[e] = h0; *(uint32_t*)&Kh[e + 2] = h1;
            *(uint32_t*)&Kl[e] = l0; *(uint32_t*)&Kl[e + 2] = l1;
            split2(vv.x, vv.y, h0, l0); split2(vv.z, vv.w, h1, l1);
            *(uint32_t*)&Vh[e] = h0; *(uint32_t*)&Vh[e + 2] = h1;
            *(uint32_t*)&Vl[e] = l0; *(uint32_t*)&Vl[e + 2] = l1;
        }
    };

    if (w >= 4) produce(0);
    __syncthreads();

    for (int t = 0; t < 64; ++t) {
        const int s = t & 1;

        if (w >= 4) {
            if (t + 1 < 64) produce(t + 1);   // fill stage s^1
        } else {
            // ---- S = Q K^T (16 rows x 64 keys) ----
            float sacc[8][4];
            #pragma unroll
            for (int nf = 0; nf < 8; ++nf)
                #pragma unroll
                for (int j = 0; j < 4; ++j) sacc[nf][j] = 0.f;

            #pragma unroll
            for (int kk = 0; kk < 8; ++kk) {
                #pragma unroll
                for (int nfp = 0; nfp < 4; ++nfp) {
                    int row = (nfp*2 + (mt >> 1))*8 + lr;          // key
                    int col = kk*16 + (mt & 1)*8;                  // hd
                    uint32_t off = (uint32_t)((s*8704 + row*136 + col)*2);
                    uint32_t bh[4], bl[4];
                    ldsm4(bh, kh_b + off);
                    ldsm4(bl, kl_b + off);
                    #pragma unroll
                    for (int h = 0; h < 2; ++h) {
                        int nf = nfp*2 + h;
                        mma16(sacc[nf], qh[kk], bh[2*h], bh[2*h+1]);
                        mma16(sacc[nf], qh[kk], bl[2*h], bl[2*h+1]);
                        mma16(sacc[nf], ql[kk], bh[2*h], bh[2*h+1]);
                    }
                }
            }

            if (t == 63) {  // causal mask, analytic
                #pragma unroll
                for (int nf = 0; nf < 8; ++nf) {
                    int key = 4032 + nf * 8 + 2 * tig;
                    if (key     > STARTP + g)     sacc[nf][0] = -1e30f;
                    if (key + 1 > STARTP + g)     sacc[nf][1] = -1e30f;
                    if (key     > STARTP + g + 8) sacc[nf][2] = -1e30f;
                    if (key + 1 > STARTP + g + 8) sacc[nf][3] = -1e30f;
                }
            }

            // ---- online softmax (rows g and g+8) ----
            float tmA = -1e30f, tmB = -1e30f;
            #pragma unroll
            for (int nf = 0; nf < 8; ++nf) {
                tmA = fmaxf(tmA, fmaxf(sacc[nf][0], sacc[nf][1]));
                tmB = fmaxf(tmB, fmaxf(sacc[nf][2], sacc[nf][3]));
            }
            tmA = fmaxf(tmA, __shfl_xor_sync(0xffffffffu, tmA, 1));
            tmA = fmaxf(tmA, __shfl_xor_sync(0xffffffffu, tmA, 2));
            tmB = fmaxf(tmB, __shfl_xor_sync(0xffffffffu, tmB, 1));
            tmB = fmaxf(tmB, __shfl_xor_sync(0xffffffffu, tmB, 2));

            float mnA = fmaxf(mA, tmA), mnB = fmaxf(mB, tmB);
            float cA = __expf(mA - mnA), cB = __expf(mB - mnB);
            float psA = 0.f, psB = 0.f;
            #pragma unroll
            for (int nf = 0; nf < 8; ++nf) {
                sacc[nf][0] = __expf(sacc[nf][0] - mnA);
                sacc[nf][1] = __expf(sacc[nf][1] - mnA);
                sacc[nf][2] = __expf(sacc[nf][2] - mnB);
                sacc[nf][3] = __expf(sacc[nf][3] - mnB);
                psA += sacc[nf][0] + sacc[nf][1];
                psB += sacc[nf][2] + sacc[nf][3];
            }
            psA += __shfl_xor_sync(0xffffffffu, psA, 1);
            psA += __shfl_xor_sync(0xffffffffu, psA, 2);
            psB += __shfl_xor_sync(0xffffffffu, psB, 1);
            psB += __shfl_xor_sync(0xffffffffu, psB, 2);
            lA = lA * cA + psA; lB = lB * cB + psB;
            mA = mnA; mB = mnB;
            #pragma unroll
            for (int i = 0; i < 16; ++i) {
                oacc[i][0] *= cA; oacc[i][1] *= cA;
                oacc[i][2] *= cB; oacc[i][3] *= cB;
            }

            // ---- O += P V (P fragments straight from sacc registers) ----
            #pragma unroll
            for (int kf = 0; kf < 4; ++kf) {
                uint32_t pah[4], pal[4];
                split2(sacc[2*kf][0],   sacc[2*kf][1],   pah[0], pal[0]);
                split2(sacc[2*kf][2],   sacc[2*kf][3],   pah[1], pal[1]);
                split2(sacc[2*kf+1][0], sacc[2*kf+1][1], pah[2], pal[2]);
                split2(sacc[2*kf+1][2], sacc[2*kf+1][3], pah[3], pal[3]);
                #pragma unroll
                for (int np = 0; np < 8; ++np) {
                    int row = kf*16 + (mt & 1)*8 + lr;             // key
                    int col = (np*2 + (mt >> 1))*8;                // d
                    uint32_t off = (uint32_t)((s*8704 + row*136 + col)*2);
                    uint32_t vh[4], vl[4];
                    ldsm4t(vh, vh_b + off);
                    ldsm4t(vl, vl_b + off);
                    #pragma unroll
                    for (int h = 0; h < 2; ++h) {
                        int nf2 = np*2 + h;
                        mma16(oacc[nf2], pah, vh[2*h], vh[2*h+1]);
                        mma16(oacc[nf2], pah, vl[2*h], vl[2*h+1]);
                        mma16(oacc[nf2], pal, vh[2*h], vh[2*h+1]);
                    }
                }
            }
        }
        __syncthreads();   // stage s consumed; stage s^1 stores visible
    }

    // ---- finalize: consumers write bf16 hi/lo planes ----
    if (w < 4) {
        float rAi = 1.f / lA, rBi = 1.f / lB;
        size_t baseA = (size_t)(b*16 + g    ) * 4096 + (kvh*4 + w) * 128;
        size_t baseB = (size_t)(b*16 + g + 8) * 4096 + (kvh*4 + w) * 128;
        #pragma unroll
        for (int nf2 = 0; nf2 < 16; ++nf2) {
            int col = nf2*8 + 2*tig;
            uint32_t h, l;
            split2(oacc[nf2][0]*rAi, oacc[nf2][1]*rAi, h, l);
            *(uint32_t*)&g_at_h[baseA + col] = h;
            *(uint32_t*)&g_at_l[baseA + col] = l;
            split2(oacc[nf2][2]*rBi, oacc[nf2][3]*rBi, h, l);
            *(uint32_t*)&g_at_h[baseB + col] = h;
            *(uint32_t*)&g_at_l[baseB + col] = l;
        }
    }
}

// ---------------------------------------------------------------------------
extern "C" void kernel_launch(void* const* d_in, const int* in_sizes, int n_in,
                              void* d_out, int out_size)
{
    const float* x  = (const float*)d_in[0];
    const float* fc = (const float*)d_in[1];
    const float* fs = (const float*)d_in[2];
    const float* ck = (const float*)d_in[4];
    const float* cv = (const float*)d_in[5];
    const float* wq = (const float*)d_in[6];
    const float* bq = (const float*)d_in[7];
    const float* wk = (const float*)d_in[8];
    const float* bk = (const float*)d_in[9];
    const float* wv = (const float*)d_in[10];
    const float* bv = (const float*)d_in[11];
    const float* wo = (const float*)d_in[12];
    const float* bo = (const float*)d_in[13];
    float* out = (float*)d_out;

    __nv_bfloat16 *x_h, *x_l, *at_h, *at_l;
    float* qkv;
    cudaGetSymbolAddress((void**)&x_h,  g_x_h);  cudaGetSymbolAddress((void**)&x_l,  g_x_l);
    cudaGetSymbolAddress((void**)&at_h, g_at_h); cudaGetSymbolAddress((void**)&at_l, g_at_l);
    cudaGetSymbolAddress((void**)&qkv,  g_qkv);

    const int gemm_smem = (2*2*64*40 + 2*2*32*72) * 2;    // 38912 B
    const int attn_smem = 4 * 2 * 8704 * 2;               // 139264 B
    cudaFuncSetAttribute(gemm_bf16x3<64, true>,
                         cudaFuncAttributeMaxDynamicSharedMemorySize, gemm_smem);
    cudaFuncSetAttribute(gemm_bf16x3<64, false>,
                         cudaFuncAttributeMaxDynamicSharedMemorySize, gemm_smem);
    cudaFuncSetAttribute(attn_bf16x3,
                         cudaFuncAttributeMaxDynamicSharedMemorySize, attn_smem);

    // 1) split x -> bf16 planes (weights are split in-GEMM)
    convert_kernel<<<1024, 256>>>(x, x_h, x_l, 256*4096/4);

    // 2) fused QKV projection + RoPE (fp32 out into g_qkv); 384 blocks
    gemm_bf16x3<64, true><<<dim3(96, 4), 128, gemm_smem>>>(
        x_h, x_l,
        wq, 4096, bq, 4096,
        wk, 1024, bk, 5120,
        wv, 1024, bv,
        qkv, 6144, fc, fs);

    // 3) attention (warp-specialized; writes bf16 hi/lo planes)
    attn_bf16x3<<<128, 256, attn_smem>>>(ck, cv);

    // 4) output projection -> d_out (fp32); 256 blocks
    gemm_bf16x3<64, false><<<dim3(64, 4), 128, gemm_smem>>>(
        at_h, at_l,
        wo, 4096, bo, 1 << 30,
        wo, 4096, bo, 1 << 30,
        wo, 4096, bo,
        out, 4096, nullptr, nullptr);
}